// round 6
// baseline (speedup 1.0000x reference)
#include <cuda_runtime.h>
#include <cuda_fp16.h>
#include <cstdint>

#define MAXN 50000
#define MAXE 1600000
#define FIN  48
#define HID  32
#define NCLS 10
#define KS   4

// ---------------- scratch (device globals) --------------------------------------
__device__ __half    g_xw1h[MAXN * KS * HID];   // [N][4][32] fp16
__device__ float     g_rb1 [MAXN * HID];        // x@root1 + bias1 (fp32)
__device__ __half    g_xw2h[MAXN * KS * NCLS];  // [N][4][10] fp16
__device__ float     g_rb2 [MAXN * NCLS];
__device__ float     g_agg1[MAXN * HID];
__device__ float     g_agg2[MAXN * NCLS];
__device__ float     g_deg [MAXN];
__device__ uint2     g_pack[MAXE];              // x: src|dst<<16,  y: frac-bits|k0
__device__ int       g_is64;

// ---------------- helpers ---------------------------------------------------------
__device__ __forceinline__ void red_add_v4(float* addr, float4 v) {
    asm volatile("red.global.add.v4.f32 [%0], {%1,%2,%3,%4};"
                 :: "l"(addr), "f"(v.x), "f"(v.y), "f"(v.z), "f"(v.w) : "memory");
}
__device__ __forceinline__ void red_add_v2(float* addr, float2 v) {
    asm volatile("red.global.add.v2.f32 [%0], {%1,%2};"
                 :: "l"(addr), "f"(v.x), "f"(v.y) : "memory");
}

// ---------------- dtype detection -------------------------------------------------
__global__ void k_detect(const void* __restrict__ ei) {
    int i = threadIdx.x;
    int hi = ((const int*)ei)[2 * i + 1];
    unsigned b = __ballot_sync(0xffffffffu, hi != 0);
    if (i == 0) g_is64 = (b == 0) ? 1 : 0;
}

// ---------------- zero agg1, agg2, deg --------------------------------------------
__global__ void k_zero(int N) {
    int tot = N * (HID + NCLS + 1);
    for (int i = blockIdx.x * blockDim.x + threadIdx.x; i < tot; i += gridDim.x * blockDim.x) {
        if (i < N * HID)               g_agg1[i] = 0.f;
        else if (i < N * (HID + NCLS)) g_agg2[i - N * HID] = 0.f;
        else                           g_deg[i - N * (HID + NCLS)] = 0.f;
    }
}

// ---------------- pack edges: decode once, also accumulate degree ------------------
__global__ void __launch_bounds__(256) k_pack(const void* __restrict__ ei,
                                              const float* __restrict__ ea, int E) {
    int e = blockIdx.x * blockDim.x + threadIdx.x;
    if (e >= E) return;
    int src, dst;
    if (g_is64) {
        src = (int)((const long long*)ei)[e];
        dst = (int)((const long long*)ei)[(long long)E + e];
    } else {
        src = ((const int*)ei)[e];
        dst = ((const int*)ei)[E + e];
    }
    float u = ea[e];
    float vv = u * (float)(KS - 1);
    float vf = floorf(vv);
    float frac = vv - vf;
    int k0 = min(max((int)vf, 0), KS - 1);
    g_pack[e] = make_uint2((unsigned)src | ((unsigned)dst << 16),
                           (__float_as_uint(frac) & ~3u) | (unsigned)k0);
    atomicAdd(&g_deg[dst], 1.0f);
}

// ---------------- layer-1 node GEMM: thread-per-node, W in smem --------------------
// smem Ws[f][j], j<128 -> W1 (k=j>>5, o=j&31), j>=128 -> root1 col (j-128)
__global__ void __launch_bounds__(256) k_xw1(const float* __restrict__ x,
                                             const float* __restrict__ W1,
                                             const float* __restrict__ root1,
                                             const float* __restrict__ bias1, int N) {
    __shared__ __align__(16) float Ws[FIN * 160];
    __shared__ float bs[HID];
    for (int i = threadIdx.x; i < FIN * 160; i += 256) {
        int f = i / 160, j = i % 160;
        float v;
        if (j < 128) { int k = j >> 5, o = j & 31; v = W1[(k * FIN + f) * HID + o]; }
        else         v = root1[f * HID + (j - 128)];
        Ws[i] = v;
    }
    if (threadIdx.x < HID) bs[threadIdx.x] = bias1[threadIdx.x];
    __syncthreads();

    for (int n = blockIdx.x * blockDim.x + threadIdx.x; n < N; n += gridDim.x * blockDim.x) {
        float xr[FIN];
        #pragma unroll
        for (int q = 0; q < FIN / 4; q++) {
            float4 v = *(const float4*)&x[n * FIN + q * 4];
            xr[q*4] = v.x; xr[q*4+1] = v.y; xr[q*4+2] = v.z; xr[q*4+3] = v.w;
        }
        // 128 xw1 outputs, 8 chunks of 16
        #pragma unroll 1
        for (int c = 0; c < 8; c++) {
            float acc[16];
            #pragma unroll
            for (int t = 0; t < 16; t++) acc[t] = 0.f;
            #pragma unroll
            for (int f = 0; f < FIN; f++) {
                const float* wrow = &Ws[f * 160 + c * 16];
                #pragma unroll
                for (int q = 0; q < 4; q++) {
                    float4 w = *(const float4*)&wrow[q * 4];
                    acc[q*4]   += xr[f] * w.x;
                    acc[q*4+1] += xr[f] * w.y;
                    acc[q*4+2] += xr[f] * w.z;
                    acc[q*4+3] += xr[f] * w.w;
                }
            }
            __half2 hbuf[8];
            #pragma unroll
            for (int t = 0; t < 8; t++)
                hbuf[t] = __floats2half2_rn(acc[t*2], acc[t*2+1]);
            uint4* dst = (uint4*)&g_xw1h[n * 128 + c * 16];
            dst[0] = *(const uint4*)&hbuf[0];
            dst[1] = *(const uint4*)&hbuf[4];
        }
        // 32 root outputs, 2 chunks of 16
        #pragma unroll 1
        for (int c = 0; c < 2; c++) {
            float acc[16];
            #pragma unroll
            for (int t = 0; t < 16; t++) acc[t] = bs[c * 16 + t];
            #pragma unroll
            for (int f = 0; f < FIN; f++) {
                const float* wrow = &Ws[f * 160 + 128 + c * 16];
                #pragma unroll
                for (int q = 0; q < 4; q++) {
                    float4 w = *(const float4*)&wrow[q * 4];
                    acc[q*4]   += xr[f] * w.x;
                    acc[q*4+1] += xr[f] * w.y;
                    acc[q*4+2] += xr[f] * w.z;
                    acc[q*4+3] += xr[f] * w.w;
                }
            }
            float4* dst = (float4*)&g_rb1[n * HID + c * 16];
            #pragma unroll
            for (int q = 0; q < 4; q++)
                dst[q] = make_float4(acc[q*4], acc[q*4+1], acc[q*4+2], acc[q*4+3]);
        }
    }
}

// ---------------- layer-1 edge scatter: 8 lanes/edge, fp16 gather, fp32 red -------
__global__ void __launch_bounds__(256) k_edge1(int E) {
    long long t = (long long)blockIdx.x * blockDim.x + threadIdx.x;
    long long e = t >> 3;
    int f4 = (int)(t & 7);
    if (e >= E) return;
    uint2 r = g_pack[e];
    int src = r.x & 0xffff;
    int dst = r.x >> 16;
    int k0  = r.y & 3;
    int k1  = min(k0 + 1, KS - 1);
    float f = __uint_as_float(r.y & ~3u);
    const __half* base = g_xw1h + src * 128;
    uint2 pa = *(const uint2*)(base + k0 * 32 + f4 * 4);
    uint2 pb = *(const uint2*)(base + k1 * 32 + f4 * 4);
    float2 A0 = __half22float2(*(const __half2*)&pa.x);
    float2 A1 = __half22float2(*(const __half2*)&pa.y);
    float2 B0 = __half22float2(*(const __half2*)&pb.x);
    float2 B1 = __half22float2(*(const __half2*)&pb.y);
    float w0 = 1.0f - f;
    float4 m = make_float4(w0 * A0.x + f * B0.x, w0 * A0.y + f * B0.y,
                           w0 * A1.x + f * B1.x, w0 * A1.y + f * B1.y);
    red_add_v4(&g_agg1[dst * HID + f4 * 4], m);
}

// ---------------- layer-2 node GEMM + fused layer-1 epilogue -----------------------
// smem W2s[o][j] padded row 52; j<40 -> W2 (k=j/10, c=j%10), j>=40 -> root2 col (j-40)
__global__ void __launch_bounds__(256) k_prep2(const float* __restrict__ W2,
                                               const float* __restrict__ root2,
                                               const float* __restrict__ bias2, int N) {
    __shared__ __align__(16) float Ws[HID * 52];
    __shared__ float bs[NCLS];
    for (int i = threadIdx.x; i < HID * 50; i += 256) {
        int o = i / 50, j = i % 50;
        float v;
        if (j < 40) { int k = j / NCLS, c = j % NCLS; v = W2[(k * HID + o) * NCLS + c]; }
        else        v = root2[o * NCLS + (j - 40)];
        Ws[o * 52 + j] = v;
    }
    if (threadIdx.x < NCLS) bs[threadIdx.x] = bias2[threadIdx.x];
    __syncthreads();

    for (int n = blockIdx.x * blockDim.x + threadIdx.x; n < N; n += gridDim.x * blockDim.x) {
        // fused layer-1 epilogue: h = elu(agg1/deg + rb1)
        float hr[HID];
        float inv = 1.0f / fmaxf(g_deg[n], 1.0f);
        #pragma unroll
        for (int q = 0; q < HID / 4; q++) {
            float4 a = *(const float4*)&g_agg1[n * HID + q * 4];
            float4 rb = *(const float4*)&g_rb1[n * HID + q * 4];
            float v0 = a.x * inv + rb.x, v1 = a.y * inv + rb.y;
            float v2 = a.z * inv + rb.z, v3 = a.w * inv + rb.w;
            hr[q*4]   = (v0 > 0.f) ? v0 : expm1f(v0);
            hr[q*4+1] = (v1 > 0.f) ? v1 : expm1f(v1);
            hr[q*4+2] = (v2 > 0.f) ? v2 : expm1f(v2);
            hr[q*4+3] = (v3 > 0.f) ? v3 : expm1f(v3);
        }
        // 40 xw2 outputs, 2 chunks of 20
        __half2 hbuf[20];
        #pragma unroll 1
        for (int c = 0; c < 2; c++) {
            float acc[20];
            #pragma unroll
            for (int t = 0; t < 20; t++) acc[t] = 0.f;
            #pragma unroll
            for (int o = 0; o < HID; o++) {
                const float* wrow = &Ws[o * 52 + c * 20];
                #pragma unroll
                for (int q = 0; q < 5; q++) {
                    float4 w = *(const float4*)&wrow[q * 4];
                    acc[q*4]   += hr[o] * w.x;
                    acc[q*4+1] += hr[o] * w.y;
                    acc[q*4+2] += hr[o] * w.z;
                    acc[q*4+3] += hr[o] * w.w;
                }
            }
            #pragma unroll
            for (int t = 0; t < 10; t++)
                hbuf[c * 10 + t] = __floats2half2_rn(acc[t*2], acc[t*2+1]);
        }
        uint4* dsth = (uint4*)&g_xw2h[n * 40];
        #pragma unroll
        for (int q = 0; q < 5; q++) dsth[q] = *(const uint4*)&hbuf[q * 4];
        // 10 rb2 outputs
        {
            float acc[10];
            #pragma unroll
            for (int t = 0; t < 10; t++) acc[t] = bs[t];
            #pragma unroll
            for (int o = 0; o < HID; o++) {
                const float* wrow = &Ws[o * 52 + 40];
                #pragma unroll
                for (int q = 0; q < 2; q++) {
                    float4 w = *(const float4*)&wrow[q * 4];
                    acc[q*4]   += hr[o] * w.x;
                    acc[q*4+1] += hr[o] * w.y;
                    acc[q*4+2] += hr[o] * w.z;
                    acc[q*4+3] += hr[o] * w.w;
                }
                float2 w2 = *(const float2*)&wrow[8];
                acc[8] += hr[o] * w2.x;
                acc[9] += hr[o] * w2.y;
            }
            float2* dst = (float2*)&g_rb2[n * NCLS];
            #pragma unroll
            for (int q = 0; q < 5; q++) dst[q] = make_float2(acc[q*2], acc[q*2+1]);
        }
    }
}

// ---------------- layer-2 edge scatter: 6 edges/warp x 5 lanes (float2) -----------
__global__ void __launch_bounds__(256) k_edge2(int E) {
    int t = blockIdx.x * blockDim.x + threadIdx.x;
    int lane = t & 31;
    int wid = t >> 5;
    int eg = lane / 5;
    int j  = lane - eg * 5;
    if (eg >= 6) return;
    long long e = (long long)wid * 6 + eg;
    if (e >= E) return;
    uint2 r = g_pack[e];
    int src = r.x & 0xffff;
    int dst = r.x >> 16;
    int k0  = r.y & 3;
    int k1  = min(k0 + 1, KS - 1);
    float f = __uint_as_float(r.y & ~3u);
    const __half* base = g_xw2h + src * 40;
    unsigned pa = *(const unsigned*)(base + k0 * 10 + j * 2);
    unsigned pb = *(const unsigned*)(base + k1 * 10 + j * 2);
    float2 A = __half22float2(*(const __half2*)&pa);
    float2 B = __half22float2(*(const __half2*)&pb);
    float w0 = 1.0f - f;
    float2 m = make_float2(w0 * A.x + f * B.x, w0 * A.y + f * B.y);
    red_add_v2(&g_agg2[dst * NCLS + j * 2], m);
}

// ---------------- final: mean + root + bias + log_softmax -------------------------
__global__ void k_out(float* __restrict__ out, int N) {
    int n = blockIdx.x * blockDim.x + threadIdx.x;
    if (n >= N) return;
    float inv = 1.0f / fmaxf(g_deg[n], 1.0f);
    float v[NCLS];
    float mx = -1e30f;
    #pragma unroll
    for (int c = 0; c < NCLS; c++) {
        v[c] = g_agg2[n * NCLS + c] * inv + g_rb2[n * NCLS + c];
        mx = fmaxf(mx, v[c]);
    }
    float s = 0.f;
    #pragma unroll
    for (int c = 0; c < NCLS; c++) s += expf(v[c] - mx);
    float ls = logf(s) + mx;
    #pragma unroll
    for (int c = 0; c < NCLS; c++) out[n * NCLS + c] = v[c] - ls;
}

// ---------------- launch -----------------------------------------------------------
extern "C" void kernel_launch(void* const* d_in, const int* in_sizes, int n_in,
                              void* d_out, int out_size) {
    const float* x     = (const float*)d_in[0];
    const void*  ei    =               d_in[1];
    const float* ea    = (const float*)d_in[2];
    const float* W1    = (const float*)d_in[3];
    const float* root1 = (const float*)d_in[4];
    const float* bias1 = (const float*)d_in[5];
    const float* W2    = (const float*)d_in[6];
    const float* root2 = (const float*)d_in[7];
    const float* bias2 = (const float*)d_in[8];
    float* out = (float*)d_out;

    int N = in_sizes[0] / FIN;     // 50000
    int E = in_sizes[2];           // 1600000

    k_detect<<<1, 32>>>(ei);
    k_zero<<<(N * (HID + NCLS + 1) + 255) / 256, 256>>>(N);
    k_pack<<<(E + 255) / 256, 256>>>(ei, ea, E);
    k_xw1<<<(N + 255) / 256, 256>>>(x, W1, root1, bias1, N);
    long long th1 = (long long)E * 8;
    k_edge1<<<(int)((th1 + 255) / 256), 256>>>(E);
    k_prep2<<<(N + 255) / 256, 256>>>(W2, root2, bias2, N);
    int warps2 = (E + 5) / 6;
    k_edge2<<<(warps2 + 7) / 8, 256>>>(E);
    k_out<<<(N + 255) / 256, 256>>>(out, N);
}